// round 1
// baseline (speedup 1.0000x reference)
#include <cuda_runtime.h>
#include <math.h>

#define BATCH 256
#define D_IN  2048
#define HID   2048
#define NSEG  10
#define D_CTX 1024
#define OUT_N 100
#define KWIN  102
#define NDEND (HID * NSEG)   /* 20480 */

/* ---------------- scratch (no allocations allowed) ---------------- */
__device__ float g_D1[(size_t)BATCH * NDEND];   /* 21 MB: dendrite acts layer 1 */
__device__ float g_D2[(size_t)BATCH * NDEND];   /* 21 MB: dendrite acts layer 2 */
__device__ float g_Y [(size_t)BATCH * HID];     /* FF pre-activation (reused)   */
__device__ float g_H1[(size_t)BATCH * HID];     /* layer-1 output (post k-win)  */
__device__ float g_H2[(size_t)BATCH * HID];     /* layer-2 output (post k-win)  */

/* ------------------------------------------------------------------
 * C[m,n] = sum_k A[m,k] * Bw[n,k] * Bm[n,k]  (+ bias[n])
 * A row-major M x K, Bw/Bm row-major N x K. Mask fused at smem fill.
 * Tile 128x128x16, 256 threads, 8x8 per thread (4+4 split layout for
 * conflict-free LDS.128).
 * ------------------------------------------------------------------ */
#define TBM 128
#define TBN 128
#define TBK 16

__global__ __launch_bounds__(256, 2)
void gemm_masked(const float* __restrict__ A,
                 const float* __restrict__ Bw,
                 const float* __restrict__ Bm,
                 const float* __restrict__ bias,
                 float* __restrict__ C,
                 int M, int N, int K)
{
    __shared__ __align__(16) float As[TBK][TBM + 4];
    __shared__ __align__(16) float Bs[TBK][TBN + 4];

    const int tid = threadIdx.x;
    const int m0  = blockIdx.y * TBM;
    const int n0  = blockIdx.x * TBN;
    const int tx  = tid & 15;   /* n direction, 16 */
    const int ty  = tid >> 4;   /* m direction, 16 */

    float acc[8][8];
#pragma unroll
    for (int i = 0; i < 8; i++)
#pragma unroll
        for (int j = 0; j < 8; j++) acc[i][j] = 0.f;

    const int lr = tid >> 2;          /* 0..63 */
    const int lc = (tid & 3) << 2;    /* 0,4,8,12 */

    const float* Ap = A  + (size_t)(m0 + lr) * K + lc;
    const float* Bp = Bw + (size_t)(n0 + lr) * K + lc;
    const float* Mp = Bm + (size_t)(n0 + lr) * K + lc;
    const size_t rstep = (size_t)64 * K;

    const int ktiles = K / TBK;
    for (int kt = 0; kt < ktiles; kt++) {
        float4 a0 = *(const float4*)(Ap);
        float4 a1 = *(const float4*)(Ap + rstep);
        float4 b0 = *(const float4*)(Bp);
        float4 b1 = *(const float4*)(Bp + rstep);
        float4 q0 = *(const float4*)(Mp);
        float4 q1 = *(const float4*)(Mp + rstep);
        __syncthreads();
        As[lc + 0][lr]      = a0.x; As[lc + 1][lr]      = a0.y;
        As[lc + 2][lr]      = a0.z; As[lc + 3][lr]      = a0.w;
        As[lc + 0][lr + 64] = a1.x; As[lc + 1][lr + 64] = a1.y;
        As[lc + 2][lr + 64] = a1.z; As[lc + 3][lr + 64] = a1.w;
        Bs[lc + 0][lr]      = b0.x * q0.x; Bs[lc + 1][lr]      = b0.y * q0.y;
        Bs[lc + 2][lr]      = b0.z * q0.z; Bs[lc + 3][lr]      = b0.w * q0.w;
        Bs[lc + 0][lr + 64] = b1.x * q1.x; Bs[lc + 1][lr + 64] = b1.y * q1.y;
        Bs[lc + 2][lr + 64] = b1.z * q1.z; Bs[lc + 3][lr + 64] = b1.w * q1.w;
        __syncthreads();
#pragma unroll
        for (int k = 0; k < TBK; k++) {
            float4 av0 = *(const float4*)&As[k][ty * 4];
            float4 av1 = *(const float4*)&As[k][64 + ty * 4];
            float4 bv0 = *(const float4*)&Bs[k][tx * 4];
            float4 bv1 = *(const float4*)&Bs[k][64 + tx * 4];
            float am[8] = {av0.x, av0.y, av0.z, av0.w, av1.x, av1.y, av1.z, av1.w};
            float bn[8] = {bv0.x, bv0.y, bv0.z, bv0.w, bv1.x, bv1.y, bv1.z, bv1.w};
#pragma unroll
            for (int i = 0; i < 8; i++)
#pragma unroll
                for (int j = 0; j < 8; j++)
                    acc[i][j] = fmaf(am[i], bn[j], acc[i][j]);
        }
        Ap += TBK; Bp += TBK; Mp += TBK;
    }

    float4 bb0, bb1;
    if (bias) {
        bb0 = *(const float4*)(bias + n0 + tx * 4);
        bb1 = *(const float4*)(bias + n0 + 64 + tx * 4);
    } else {
        bb0 = make_float4(0.f, 0.f, 0.f, 0.f);
        bb1 = bb0;
    }

#pragma unroll
    for (int i = 0; i < 8; i++) {
        const int m = m0 + ((i < 4) ? (ty * 4 + i) : (64 + ty * 4 + i - 4));
        float* Crow = C + (size_t)m * N;
        float4 o0, o1;
        o0.x = acc[i][0] + bb0.x; o0.y = acc[i][1] + bb0.y;
        o0.z = acc[i][2] + bb0.z; o0.w = acc[i][3] + bb0.w;
        o1.x = acc[i][4] + bb1.x; o1.y = acc[i][5] + bb1.y;
        o1.z = acc[i][6] + bb1.z; o1.w = acc[i][7] + bb1.w;
        *(float4*)(Crow + n0 + tx * 4)      = o0;
        *(float4*)(Crow + n0 + 64 + tx * 4) = o1;
    }
}

/* ------------------------------------------------------------------
 * Per batch-row: abs-argmax dendrite segment -> sigmoid gate -> y*gate,
 * then exact top-K (K=102 of 2048) via 32-step binary search on
 * order-preserving uint keys. One block per row.
 * ------------------------------------------------------------------ */
__global__ __launch_bounds__(256)
void gate_kwinners(const float* __restrict__ Y,
                   const float* __restrict__ D,
                   float* __restrict__ H)
{
    const int b   = blockIdx.x;
    const int tid = threadIdx.x;
    __shared__ float        sv[HID];
    __shared__ unsigned int sk[HID];
    __shared__ int scnt;

    const float* drow = D + (size_t)b * NDEND;
    const float* yrow = Y + (size_t)b * HID;

    for (int u = tid; u < HID; u += 256) {
        const float* dp = drow + u * NSEG;
        float best  = dp[0];
        float besta = fabsf(best);
#pragma unroll
        for (int s = 1; s < NSEG; s++) {
            float v = dp[s], a = fabsf(v);
            if (a > besta) { besta = a; best = v; }   /* first-max, like argmax */
        }
        float gate = 1.f / (1.f + expf(-best));
        float v = yrow[u] * gate;
        sv[u] = v;
        unsigned int ui = __float_as_uint(v);
        sk[u] = (ui & 0x80000000u) ? ~ui : (ui | 0x80000000u);
    }
    __syncthreads();

    unsigned int T = 0u;                     /* becomes the KWIN-th largest key */
    for (int bit = 31; bit >= 0; bit--) {
        const unsigned int cand = T | (1u << bit);
        if (tid == 0) scnt = 0;
        __syncthreads();
        int c = 0;
        for (int u = tid; u < HID; u += 256) c += (sk[u] >= cand) ? 1 : 0;
        for (int o = 16; o; o >>= 1) c += __shfl_down_sync(0xffffffffu, c, o);
        if ((tid & 31) == 0) atomicAdd(&scnt, c);
        __syncthreads();
        if (scnt >= KWIN) T = cand;
        __syncthreads();
    }

    for (int u = tid; u < HID; u += 256)
        H[(size_t)b * HID + u] = (sk[u] >= T) ? sv[u] : 0.f;
}

/* ------------------------------------------------------------------
 * Dale head: out[b,o] = dot(h, Wex[o]) - Wei[o]*dot(h, Wix) + b_out[o]
 * One block per batch row.
 * ------------------------------------------------------------------ */
__global__ __launch_bounds__(128)
void head_kernel(const float* __restrict__ H,
                 const float* __restrict__ Wex,
                 const float* __restrict__ Wix,
                 const float* __restrict__ Wei,
                 const float* __restrict__ bo,
                 float* __restrict__ out)
{
    const int b   = blockIdx.x;
    const int tid = threadIdx.x;
    __shared__ __align__(16) float sh[HID];
    __shared__ float sred[4];

    for (int k = tid; k < HID; k += 128) sh[k] = H[(size_t)b * HID + k];
    __syncthreads();

    float p = 0.f;
    for (int k = tid; k < HID; k += 128) p += sh[k] * Wix[k];
    for (int o = 16; o; o >>= 1) p += __shfl_down_sync(0xffffffffu, p, o);
    if ((tid & 31) == 0) sred[tid >> 5] = p;
    __syncthreads();
    const float S = sred[0] + sred[1] + sred[2] + sred[3];

    if (tid < OUT_N) {
        const float* wrow = Wex + (size_t)tid * HID;
        float acc = 0.f;
#pragma unroll 4
        for (int k = 0; k < HID; k += 4) {
            float4 w = *(const float4*)(wrow + k);
            acc = fmaf(sh[k + 0], w.x, acc);
            acc = fmaf(sh[k + 1], w.y, acc);
            acc = fmaf(sh[k + 2], w.z, acc);
            acc = fmaf(sh[k + 3], w.w, acc);
        }
        out[(size_t)b * OUT_N + tid] = acc - Wei[tid] * S + bo[tid];
    }
}

/* ------------------------------------------------------------------ */
extern "C" void kernel_launch(void* const* d_in, const int* in_sizes, int n_in,
                              void* d_out, int out_size)
{
    (void)in_sizes; (void)n_in; (void)out_size;
    const float* x      = (const float*)d_in[0];
    const float* ctx    = (const float*)d_in[1];
    const float* W1     = (const float*)d_in[2];
    const float* b1     = (const float*)d_in[3];
    const float* segW1  = (const float*)d_in[4];
    const float* maskW1 = (const float*)d_in[5];
    const float* maskS1 = (const float*)d_in[6];
    const float* W2     = (const float*)d_in[7];
    const float* b2     = (const float*)d_in[8];
    const float* segW2  = (const float*)d_in[9];
    const float* maskW2 = (const float*)d_in[10];
    const float* maskS2 = (const float*)d_in[11];
    const float* Wex    = (const float*)d_in[12];
    const float* Wix    = (const float*)d_in[13];
    const float* Wei    = (const float*)d_in[14];
    const float* bo     = (const float*)d_in[15];
    float* out = (float*)d_out;

    float *pD1, *pD2, *pY, *pH1, *pH2;
    cudaGetSymbolAddress((void**)&pD1, g_D1);
    cudaGetSymbolAddress((void**)&pD2, g_D2);
    cudaGetSymbolAddress((void**)&pY,  g_Y);
    cudaGetSymbolAddress((void**)&pH1, g_H1);
    cudaGetSymbolAddress((void**)&pH2, g_H2);

    const dim3 blk(256);
    const dim3 gDend(NDEND / TBN, BATCH / TBM);  /* 160 x 2 */
    const dim3 gFF(HID / TBN, BATCH / TBM);      /* 16 x 2  */

    /* Dendrites for BOTH layers depend only on context -> run up front. */
    gemm_masked<<<gDend, blk>>>(ctx, segW1, maskS1, nullptr, pD1, BATCH, NDEND, D_CTX);
    gemm_masked<<<gDend, blk>>>(ctx, segW2, maskS2, nullptr, pD2, BATCH, NDEND, D_CTX);

    /* Layer 1 */
    gemm_masked<<<gFF, blk>>>(x, W1, maskW1, b1, pY, BATCH, HID, D_IN);
    gate_kwinners<<<BATCH, 256>>>(pY, pD1, pH1);

    /* Layer 2 */
    gemm_masked<<<gFF, blk>>>(pH1, W2, maskW2, b2, pY, BATCH, HID, HID);
    gate_kwinners<<<BATCH, 256>>>(pY, pD2, pH2);

    /* Dale output head */
    head_kernel<<<BATCH, 128>>>(pH2, Wex, Wix, Wei, bo, out);
}

// round 2
// speedup vs baseline: 1.3544x; 1.3544x over previous
#include <cuda_runtime.h>
#include <math.h>

#define BATCH 256
#define D_IN  2048
#define HID   2048
#define NSEG  10
#define D_CTX 1024
#define OUT_N 100
#define KWIN  102
#define NDEND (HID * NSEG)   /* 20480 */

#define SLOTS_D 112   /* dendrite rows: Binom(1024,.05) mean 51.2, sd 7.0  -> 8.7 sd margin */
#define SLOTS_F 160   /* FF rows:       Binom(2048,.05) mean 102.4, sd 9.9 -> 5.8 sd margin */

/* ---------------- scratch (no allocations allowed) ---------------- */
__device__ float g_CT [(size_t)D_CTX * BATCH];      /* ctx^T  [1024][256]  */
__device__ float g_XT [(size_t)D_IN  * BATCH];      /* x^T    [2048][256]  */
__device__ float g_D1t[(size_t)NDEND * BATCH];      /* dendrites L1 [n][b] */
__device__ float g_D2t[(size_t)NDEND * BATCH];      /* dendrites L2 [n][b] */
__device__ float g_Yt [(size_t)HID   * BATCH];      /* FF preact [u][b]    */
__device__ float g_V  [(size_t)BATCH * HID];        /* gated values [b][u] */
__device__ float g_H  [(size_t)BATCH * HID];        /* kwin output  [b][u] */
__device__ float g_HT [(size_t)HID   * BATCH];      /* kwin output  [u][b] */

/* compacted sparse weights */
__device__ float          g_dv1[(size_t)NDEND * SLOTS_D];
__device__ unsigned short g_di1[(size_t)NDEND * SLOTS_D];
__device__ int            g_dc1[NDEND];
__device__ float          g_dv2[(size_t)NDEND * SLOTS_D];
__device__ unsigned short g_di2[(size_t)NDEND * SLOTS_D];
__device__ int            g_dc2[NDEND];
__device__ float          g_fv1[(size_t)HID * SLOTS_F];
__device__ unsigned short g_fi1[(size_t)HID * SLOTS_F];
__device__ int            g_fc1[HID];
__device__ float          g_fv2[(size_t)HID * SLOTS_F];
__device__ unsigned short g_fi2[(size_t)HID * SLOTS_F];
__device__ int            g_fc2[HID];

/* ------------------------------------------------------------------
 * 32x32 tiled transpose: out[c][r] = in[r][c], in is rows x cols.
 * ------------------------------------------------------------------ */
__global__ __launch_bounds__(256)
void transpose_k(const float* __restrict__ in, float* __restrict__ out,
                 int rows, int cols)
{
    __shared__ float t[32][33];
    const int cb = blockIdx.x * 32, rb = blockIdx.y * 32;
    const int tx = threadIdx.x, ty = threadIdx.y;  /* 32 x 8 */
#pragma unroll
    for (int i = 0; i < 32; i += 8) {
        int r = rb + ty + i, c = cb + tx;
        if (r < rows && c < cols) t[ty + i][tx] = in[(size_t)r * cols + c];
    }
    __syncthreads();
#pragma unroll
    for (int i = 0; i < 32; i += 8) {
        int c = cb + ty + i, r = rb + tx;
        if (c < cols && r < rows) out[(size_t)c * rows + r] = t[tx][ty + i];
    }
}

/* ------------------------------------------------------------------
 * Compaction: one warp per weight row. Emit (val, idx) where mask!=0.
 * ------------------------------------------------------------------ */
template<int SLOTS>
__global__ __launch_bounds__(256)
void compact_k(const float* __restrict__ W, const float* __restrict__ M,
               float* __restrict__ vals, unsigned short* __restrict__ idxs,
               int* __restrict__ cnt, int R, int K)
{
    const int row  = blockIdx.x * 8 + (threadIdx.x >> 5);
    if (row >= R) return;
    const int lane = threadIdx.x & 31;
    const float* mr = M + (size_t)row * K;
    const float* wr = W + (size_t)row * K;
    float* vo = vals + (size_t)row * SLOTS;
    unsigned short* io = idxs + (size_t)row * SLOTS;

    int base = 0;
    for (int c0 = 0; c0 < K; c0 += 32) {
        const float m = mr[c0 + lane];
        const unsigned bal = __ballot_sync(0xffffffffu, m != 0.f);
        if (m != 0.f) {
            const int pos = base + __popc(bal & ((1u << lane) - 1u));
            if (pos < SLOTS) {
                vo[pos] = wr[c0 + lane];       /* weight loaded only when kept */
                io[pos] = (unsigned short)(c0 + lane);
            }
        }
        base += __popc(bal);
    }
    if (lane == 0) cnt[row] = base < SLOTS ? base : SLOTS;
}

/* ------------------------------------------------------------------
 * Sparse GEMM:  Ct[n][b] = sum_j val[n][j] * AT[idx[n][j]][b]
 * AT [KDIM][256] cached in smem as a batch chunk of BSUB columns
 * (padded row stride BSUB+1). One warp = BSUB batch lanes x (32/BSUB)
 * nz lanes; each warp owns rows strided by 8.
 * ------------------------------------------------------------------ */
template<int BSUB, int SLOTS, int KDIM>
__global__ __launch_bounds__(256)
void sparse_mm(const float* __restrict__ AT,
               const float* __restrict__ vals,
               const unsigned short* __restrict__ idxs,
               const int* __restrict__ cnt,
               float* __restrict__ Ct,
               int R, int rows_per_blk)
{
    constexpr int JL   = 32 / BSUB;                 /* nz lanes per warp   */
    constexpr int PAD  = BSUB + 1;
    constexpr size_t SAT_BYTES = (size_t)KDIM * PAD * 4;

    extern __shared__ __align__(16) char smem[];
    float*  sA    = (float*)smem;
    float2* stage = (float2*)(smem + SAT_BYTES);    /* [8 warps][SLOTS] */

    const int tid  = threadIdx.x;
    const int wid  = tid >> 5;
    const int lane = tid & 31;
    const int bl   = lane & (BSUB - 1);
    const int jj   = lane >> (BSUB == 16 ? 4 : 5);
    const int b0   = blockIdx.x * BSUB;

    /* fill the AT batch-chunk */
    for (int i = tid; i < KDIM * BSUB; i += 256) {
        const int k = i / BSUB, bc = i % BSUB;
        sA[k * PAD + bc] = AT[(size_t)k * BATCH + b0 + bc];
    }
    __syncthreads();

    const int rowbase = blockIdx.y * rows_per_blk;
    int rowend = rowbase + rows_per_blk; if (rowend > R) rowend = R;

    float2* st = stage + (size_t)wid * SLOTS;
    const char* blptr = smem + (bl << 2);

    for (int n = rowbase + wid; n < rowend; n += 8) {
        const int c = cnt[n];
        const float* vp = vals + (size_t)n * SLOTS;
        const unsigned short* ip = idxs + (size_t)n * SLOTS;
        for (int t = lane; t < c; t += 32)
            st[t] = make_float2(vp[t], __int_as_float(((int)ip[t]) * (PAD * 4)));
        __syncwarp();

        float acc0 = 0.f, acc1 = 0.f;
        int j = jj;
        for (; j + JL < c; j += 2 * JL) {
            const float2 p0 = st[j];
            const float2 p1 = st[j + JL];
            acc0 = fmaf(*(const float*)(blptr + __float_as_int(p0.y)), p0.x, acc0);
            acc1 = fmaf(*(const float*)(blptr + __float_as_int(p1.y)), p1.x, acc1);
        }
        if (j < c) {
            const float2 p0 = st[j];
            acc0 = fmaf(*(const float*)(blptr + __float_as_int(p0.y)), p0.x, acc0);
        }
        float acc = acc0 + acc1;
        if (BSUB == 16) {
            acc += __shfl_xor_sync(0xffffffffu, acc, 16);
            if (jj == 0) Ct[(size_t)n * BATCH + b0 + bl] = acc;
        } else {
            Ct[(size_t)n * BATCH + b0 + bl] = acc;
        }
        __syncwarp();
    }
}

/* ------------------------------------------------------------------
 * Gate: per unit u (block), per batch b (thread):
 * first-occurrence abs-argmax over 10 segments -> sigmoid -> y*gate.
 * Reads Dt/Yt coalesced, writes V[b][u] (scattered, tiny matrix).
 * ------------------------------------------------------------------ */
__global__ __launch_bounds__(256)
void gate_k(const float* __restrict__ Yt, const float* __restrict__ Dt,
            const float* __restrict__ bias, float* __restrict__ V)
{
    const int u = blockIdx.x;
    const int b = threadIdx.x;
    const float* dp = Dt + (size_t)u * NSEG * BATCH + b;
    float best = dp[0];
    float besta = fabsf(best);
#pragma unroll
    for (int s = 1; s < NSEG; s++) {
        const float v = dp[(size_t)s * BATCH];
        const float a = fabsf(v);
        if (a > besta) { besta = a; best = v; }
    }
    const float y = Yt[(size_t)u * BATCH + b] + bias[u];
    const float gate = 1.f / (1.f + expf(-best));
    V[(size_t)b * HID + u] = y * gate;
}

/* ------------------------------------------------------------------
 * Exact top-K per batch row (K=102 of 2048): 32-step binary search on
 * order-preserving uint keys. Writes H[b][u] and HT[u][b].
 * ------------------------------------------------------------------ */
__global__ __launch_bounds__(256)
void topk_k(const float* __restrict__ V, float* __restrict__ H,
            float* __restrict__ HT)
{
    const int b   = blockIdx.x;
    const int tid = threadIdx.x;
    __shared__ float        sv[HID];
    __shared__ unsigned int sk[HID];
    __shared__ int scnt;

    for (int u = tid; u < HID; u += 256) {
        const float v = V[(size_t)b * HID + u];
        sv[u] = v;
        const unsigned int ui = __float_as_uint(v);
        sk[u] = (ui & 0x80000000u) ? ~ui : (ui | 0x80000000u);
    }
    __syncthreads();

    unsigned int T = 0u;
    for (int bit = 31; bit >= 0; bit--) {
        const unsigned int cand = T | (1u << bit);
        if (tid == 0) scnt = 0;
        __syncthreads();
        int c = 0;
        for (int u = tid; u < HID; u += 256) c += (sk[u] >= cand) ? 1 : 0;
        for (int o = 16; o; o >>= 1) c += __shfl_down_sync(0xffffffffu, c, o);
        if ((tid & 31) == 0) atomicAdd(&scnt, c);
        __syncthreads();
        if (scnt >= KWIN) T = cand;
        __syncthreads();
    }

    for (int u = tid; u < HID; u += 256) {
        const float o = (sk[u] >= T) ? sv[u] : 0.f;
        H [(size_t)b * HID   + u] = o;
        HT[(size_t)u * BATCH + b] = o;
    }
}

/* ------------------------------------------------------------------
 * Dale head: out[b,o] = dot(h, Wex[o]) - Wei[o]*dot(h, Wix) + b_out[o]
 * ------------------------------------------------------------------ */
__global__ __launch_bounds__(128)
void head_k(const float* __restrict__ H,
            const float* __restrict__ Wex, const float* __restrict__ Wix,
            const float* __restrict__ Wei, const float* __restrict__ bo,
            float* __restrict__ out)
{
    const int b   = blockIdx.x;
    const int tid = threadIdx.x;
    __shared__ __align__(16) float sh[HID];
    __shared__ float sred[4];

    for (int k = tid; k < HID; k += 128) sh[k] = H[(size_t)b * HID + k];
    __syncthreads();

    float p = 0.f;
    for (int k = tid; k < HID; k += 128) p += sh[k] * Wix[k];
    for (int o = 16; o; o >>= 1) p += __shfl_down_sync(0xffffffffu, p, o);
    if ((tid & 31) == 0) sred[tid >> 5] = p;
    __syncthreads();
    const float S = sred[0] + sred[1] + sred[2] + sred[3];

    if (tid < OUT_N) {
        const float* wrow = Wex + (size_t)tid * HID;
        float acc = 0.f;
#pragma unroll 4
        for (int k = 0; k < HID; k += 4) {
            const float4 w = *(const float4*)(wrow + k);
            acc = fmaf(sh[k + 0], w.x, acc);
            acc = fmaf(sh[k + 1], w.y, acc);
            acc = fmaf(sh[k + 2], w.z, acc);
            acc = fmaf(sh[k + 3], w.w, acc);
        }
        out[(size_t)b * OUT_N + tid] = acc - Wei[tid] * S + bo[tid];
    }
}

/* ------------------------------------------------------------------ */
extern "C" void kernel_launch(void* const* d_in, const int* in_sizes, int n_in,
                              void* d_out, int out_size)
{
    (void)in_sizes; (void)n_in; (void)out_size;
    const float* x      = (const float*)d_in[0];
    const float* ctx    = (const float*)d_in[1];
    const float* W1     = (const float*)d_in[2];
    const float* b1     = (const float*)d_in[3];
    const float* segW1  = (const float*)d_in[4];
    const float* maskW1 = (const float*)d_in[5];
    const float* maskS1 = (const float*)d_in[6];
    const float* W2     = (const float*)d_in[7];
    const float* b2     = (const float*)d_in[8];
    const float* segW2  = (const float*)d_in[9];
    const float* maskW2 = (const float*)d_in[10];
    const float* maskS2 = (const float*)d_in[11];
    const float* Wex    = (const float*)d_in[12];
    const float* Wix    = (const float*)d_in[13];
    const float* Wei    = (const float*)d_in[14];
    const float* bo     = (const float*)d_in[15];
    float* out = (float*)d_out;

    float *pCT, *pXT, *pD1, *pD2, *pYt, *pV, *pH, *pHT;
    cudaGetSymbolAddress((void**)&pCT, g_CT);
    cudaGetSymbolAddress((void**)&pXT, g_XT);
    cudaGetSymbolAddress((void**)&pD1, g_D1t);
    cudaGetSymbolAddress((void**)&pD2, g_D2t);
    cudaGetSymbolAddress((void**)&pYt, g_Yt);
    cudaGetSymbolAddress((void**)&pV,  g_V);
    cudaGetSymbolAddress((void**)&pH,  g_H);
    cudaGetSymbolAddress((void**)&pHT, g_HT);

    float *dv1, *dv2, *fv1, *fv2;
    unsigned short *di1, *di2, *fi1, *fi2;
    int *dc1, *dc2, *fc1, *fc2;
    cudaGetSymbolAddress((void**)&dv1, g_dv1); cudaGetSymbolAddress((void**)&di1, g_di1);
    cudaGetSymbolAddress((void**)&dc1, g_dc1);
    cudaGetSymbolAddress((void**)&dv2, g_dv2); cudaGetSymbolAddress((void**)&di2, g_di2);
    cudaGetSymbolAddress((void**)&dc2, g_dc2);
    cudaGetSymbolAddress((void**)&fv1, g_fv1); cudaGetSymbolAddress((void**)&fi1, g_fi1);
    cudaGetSymbolAddress((void**)&fc1, g_fc1);
    cudaGetSymbolAddress((void**)&fv2, g_fv2); cudaGetSymbolAddress((void**)&fi2, g_fi2);
    cudaGetSymbolAddress((void**)&fc2, g_fc2);

    /* dynamic smem sizes */
    const int smemD = D_CTX * 17 * 4 + 8 * SLOTS_D * 8;  /* 69632 + 7168  = 76800  */
    const int smemF = D_IN  * 17 * 4 + 8 * SLOTS_F * 8;  /* 139264 + 10240 = 149504 */
    cudaFuncSetAttribute((const void*)sparse_mm<16, SLOTS_D, D_CTX>,
                         cudaFuncAttributeMaxDynamicSharedMemorySize, smemD);
    cudaFuncSetAttribute((const void*)sparse_mm<16, SLOTS_F, D_IN>,
                         cudaFuncAttributeMaxDynamicSharedMemorySize, smemF);

    /* transposes (activations) */
    transpose_k<<<dim3(D_CTX / 32, BATCH / 32), dim3(32, 8)>>>(ctx, pCT, BATCH, D_CTX);
    transpose_k<<<dim3(D_IN  / 32, BATCH / 32), dim3(32, 8)>>>(x,   pXT, BATCH, D_IN);

    /* weight compaction (95% sparse masks) */
    compact_k<SLOTS_D><<<(NDEND + 7) / 8, 256>>>(segW1, maskS1, dv1, di1, dc1, NDEND, D_CTX);
    compact_k<SLOTS_D><<<(NDEND + 7) / 8, 256>>>(segW2, maskS2, dv2, di2, dc2, NDEND, D_CTX);
    compact_k<SLOTS_F><<<(HID   + 7) / 8, 256>>>(W1,    maskW1, fv1, fi1, fc1, HID, D_IN);
    compact_k<SLOTS_F><<<(HID   + 7) / 8, 256>>>(W2,    maskW2, fv2, fi2, fc2, HID, HID);

    /* dendrites for BOTH layers depend only on context */
    const int rpbD = (NDEND + 17) / 18;  /* 1138 */
    sparse_mm<16, SLOTS_D, D_CTX><<<dim3(BATCH / 16, 18), 256, smemD>>>(
        pCT, dv1, di1, dc1, pD1, NDEND, rpbD);
    sparse_mm<16, SLOTS_D, D_CTX><<<dim3(BATCH / 16, 18), 256, smemD>>>(
        pCT, dv2, di2, dc2, pD2, NDEND, rpbD);

    const int rpbF = (HID + 8) / 9;      /* 228 */

    /* layer 1 */
    sparse_mm<16, SLOTS_F, D_IN><<<dim3(BATCH / 16, 9), 256, smemF>>>(
        pXT, fv1, fi1, fc1, pYt, HID, rpbF);
    gate_k<<<HID, 256>>>(pYt, pD1, b1, pV);
    topk_k<<<BATCH, 256>>>(pV, pH, pHT);

    /* layer 2 (input = H1^T) */
    sparse_mm<16, SLOTS_F, D_IN><<<dim3(BATCH / 16, 9), 256, smemF>>>(
        pHT, fv2, fi2, fc2, pYt, HID, rpbF);
    gate_k<<<HID, 256>>>(pYt, pD2, b2, pV);
    topk_k<<<BATCH, 256>>>(pV, pH, pHT);

    /* Dale output head */
    head_k<<<BATCH, 128>>>(pH, Wex, Wix, Wei, bo, out);
}